// round 3
// baseline (speedup 1.0000x reference)
#include <cuda_runtime.h>
#include <cuda_bf16.h>
#include <cstdint>

// Problem constants
#define BB 2048   // batch
#define BP 2058   // padded batch (147 CTAs * 14 rows)
#define TT 64     // timesteps
#define HH 64     // LSTM hidden
#define GG 256    // 4*H gates
#define NL 8      // LSTM layers
#define BT 14     // batch rows per CTA
#define NCTA 147

// Ping-pong inter-layer buffers, layout [T, BP, H] (layer0 input uses [T, BP, 16])
__device__ float g_bufA[(size_t)TT * BP * HH + 256];
__device__ float g_bufB[(size_t)TT * BP * HH + 256];

__device__ __forceinline__ float* bufptr(int s) { return s ? g_bufB : g_bufA; }

__device__ __forceinline__ float sigm(float x) {
    return __fdividef(1.0f, 1.0f + __expf(-x));
}
__device__ __forceinline__ float tanh_(float x) {
    return __fdividef(2.0f, 1.0f + __expf(-2.0f * x)) - 1.0f;
}

// ---- packed f32x2 helpers (Blackwell FFMA2; PTX-only) ----
__device__ __forceinline__ void ffma2(uint64_t& d, uint64_t a, uint64_t b) {
    asm("fma.rn.f32x2 %0, %1, %2, %0;" : "+l"(d) : "l"(a), "l"(b));
}
__device__ __forceinline__ uint64_t pack2(float lo, float hi) {
    uint64_t r;
    asm("mov.b64 %0, {%1, %2};" : "=l"(r) : "f"(lo), "f"(hi));
    return r;
}
__device__ __forceinline__ float hsum2(uint64_t v) {
    float lo, hi;
    asm("mov.b64 {%0, %1}, %2;" : "=f"(lo), "=f"(hi) : "l"(v));
    return lo + hi;
}

// ---------------------------------------------------------------------------
// Input MLP: x[B,T,2] -> relu(x@w1^T+b1)@w2^T+b2 -> g_bufA as [T,BP,16]
// ---------------------------------------------------------------------------
__global__ void mlp_in_kernel(const float* __restrict__ x,
                              const float* __restrict__ w1, const float* __restrict__ b1,
                              const float* __restrict__ w2, const float* __restrict__ b2)
{
    __shared__ float s_w1[16][2], s_b1[16], s_w2[16][16], s_b2[16];
    int tid = threadIdx.x;
    if (tid < 32) { s_w1[tid / 2][tid % 2] = w1[tid]; }
    if (tid < 16) { s_b1[tid] = b1[tid]; s_b2[tid] = b2[tid]; }
    if (tid >= 32 && tid < 32 + 256) {
        int i = tid - 32;
        s_w2[i / 16][i % 16] = w2[i];
    }
    __syncthreads();

    int idx = blockIdx.x * blockDim.x + tid;      // 0 .. B*T-1, idx = b*T + t
    int b = idx / TT;
    int t = idx % TT;
    float x0 = x[(size_t)idx * 2 + 0];
    float x1 = x[(size_t)idx * 2 + 1];

    float h1[16];
#pragma unroll
    for (int j = 0; j < 16; j++) {
        float v = fmaf(s_w1[j][0], x0, fmaf(s_w1[j][1], x1, s_b1[j]));
        h1[j] = fmaxf(v, 0.0f);
    }
    float* dst = g_bufA + (size_t)t * BP * 16 + (size_t)b * 16;
#pragma unroll
    for (int j = 0; j < 16; j++) {
        float o = s_b2[j];
#pragma unroll
        for (int k = 0; k < 16; k++) o = fmaf(s_w2[j][k], h1[k], o);
        dst[j] = o;
    }
}

// ---------------------------------------------------------------------------
// One LSTM layer, 512 threads. Gate column j is split across thread j (low
// half of K) and thread j+256 (high half of K), K = concat(x_t[I], h[64]).
// Each thread holds its KH/2 weight pairs in 64-bit registers for the whole
// layer (~64 regs) -> 4 warps/SMSP for latency hiding. Partial sums folded
// through s_gpart in the elementwise phase.
// ---------------------------------------------------------------------------
template <int I>
__global__ void __launch_bounds__(512, 1)
lstm_kernel(int insel, int outsel,
            const float* __restrict__ w_ih, const float* __restrict__ w_hh,
            const float* __restrict__ b_ih, const float* __restrict__ b_hh)
{
    constexpr int KTOT = I + HH;
    constexpr int KH   = KTOT / 2;        // per-thread K range (I=64 -> 64, I=16 -> 40)

    __shared__ __align__(16) float s_act[BT][KTOT];       // [x_t | h]
    __shared__ __align__(16) float s_c[BT][HH];
    __shared__ __align__(16) float s_gpart[2][BT][GG];    // K-split partials

    const float* in  = bufptr(insel);
    float*       out = bufptr(outsel);
    const int tid  = threadIdx.x;
    const int j    = tid & 255;           // gate column
    const int half = tid >> 8;            // K half
    const int b0   = blockIdx.x * BT;

    // Per-thread weight pairs for k in [half*KH, (half+1)*KH)
    uint64_t w2[KH / 2];
#pragma unroll
    for (int kk = 0; kk < KH; kk += 2) {
        int k0 = half * KH + kk;
        int k1 = k0 + 1;
        float a = (k0 < I) ? w_ih[(size_t)j * I + k0] : w_hh[(size_t)j * HH + (k0 - I)];
        float b = (k1 < I) ? w_ih[(size_t)j * I + k1] : w_hh[(size_t)j * HH + (k1 - I)];
        w2[kk / 2] = pack2(a, b);
    }
    const uint64_t bias2 = (half == 0) ? pack2(b_ih[j] + b_hh[j], 0.0f) : 0ull;

    // h0 = c0 = 0
    for (int i = tid; i < BT * HH; i += 512) {
        (&s_act[0][0] + 0)[0] = (&s_act[0][0])[0];  // no-op keep
    }
    for (int i = tid; i < BT; i += 512) {}
    // zero h cols and c
    for (int i = tid; i < BT * HH; i += 512) {
        int r = i / HH, u = i % HH;
        s_act[r][I + u] = 0.0f;
        s_c[r][u] = 0.0f;
    }
    // stage x_0
    {
        const float4* src = reinterpret_cast<const float4*>(in + (size_t)0 * BP * I + (size_t)b0 * I);
        for (int i = tid; i < BT * I / 4; i += 512) {
            float4 v = src[i];
            int r = (4 * i) / I, k = (4 * i) % I;
            *reinterpret_cast<float4*>(&s_act[r][k]) = v;
        }
    }
    __syncthreads();

    for (int t = 0; t < TT; t++) {
        // gates partial: sum over my K half (thread = one gate column, one half)
        uint64_t acc[BT];
#pragma unroll
        for (int r = 0; r < BT; r++) acc[r] = bias2;

        const float* actbase = &s_act[0][half * KH];
#pragma unroll
        for (int kk = 0; kk < KH; kk += 4) {
#pragma unroll
            for (int r = 0; r < BT; r++) {
                ulonglong2 v = *reinterpret_cast<const ulonglong2*>(actbase + (size_t)r * KTOT + kk); // LDS.128 bcast
                ffma2(acc[r], v.x, w2[kk / 2]);
                ffma2(acc[r], v.y, w2[kk / 2 + 1]);
            }
        }
#pragma unroll
        for (int r = 0; r < BT; r++) s_gpart[half][r][j] = hsum2(acc[r]);
        __syncthreads();

        // elementwise update: BT*64 = 896 (row, unit) pairs over 512 threads
#pragma unroll
        for (int p = 0; p < 2; p++) {
            int ul = p * 512 + tid;
            if (ul < BT * HH) {
                int r  = ul >> 6;
                int u  = ul & 63;
                float gi = s_gpart[0][r][u]       + s_gpart[1][r][u];
                float gf = s_gpart[0][r][64 + u]  + s_gpart[1][r][64 + u];
                float gg = s_gpart[0][r][128 + u] + s_gpart[1][r][128 + u];
                float go = s_gpart[0][r][192 + u] + s_gpart[1][r][192 + u];
                float iv = sigm(gi);
                float fv = sigm(gf);
                float gv = tanh_(gg);
                float ov = sigm(go);
                float c  = fmaf(fv, s_c[r][u], iv * gv);
                float h  = ov * tanh_(c);
                s_c[r][u] = c;
                s_act[r][I + u] = h;
                out[(size_t)t * BP * HH + (size_t)(b0 + r) * HH + u] = h;
            }
        }
        // stage x_{t+1} (mainloop of step t finished: guarded by sync above)
        if (t + 1 < TT) {
            const float4* src = reinterpret_cast<const float4*>(in + (size_t)(t + 1) * BP * I + (size_t)b0 * I);
            for (int i = tid; i < BT * I / 4; i += 512) {
                float4 v = src[i];
                int r = (4 * i) / I, k = (4 * i) % I;
                *reinterpret_cast<float4*>(&s_act[r][k]) = v;
            }
        }
        __syncthreads();
    }
}

// ---------------------------------------------------------------------------
// Output MLP: h[T,BP,64] -> relu(h@wo1^T+bo1)@wo2^T+bo2 -> out[B,T,4]
// ---------------------------------------------------------------------------
__global__ void mlp_out_kernel(int insel,
                               const float* __restrict__ wo1, const float* __restrict__ bo1,
                               const float* __restrict__ wo2, const float* __restrict__ bo2,
                               float* __restrict__ outp)
{
    __shared__ float s_w1[32][64];
    __shared__ float s_b1[32];
    __shared__ float s_w2[4][32];
    __shared__ float s_b2[4];
    int tid = threadIdx.x;
    for (int i = tid; i < 32 * 64; i += 256) s_w1[i / 64][i % 64] = wo1[i];
    if (tid < 32) s_b1[tid] = bo1[tid];
    if (tid < 128) s_w2[tid / 32][tid % 32] = wo2[tid];
    if (tid < 4) s_b2[tid] = bo2[tid];
    __syncthreads();

    const float* in = bufptr(insel);
    int idx = blockIdx.x * blockDim.x + tid;   // idx = t*B + b (coalesced h reads)
    int t = idx / BB;
    int b = idx % BB;

    float h[64];
    const float4* src = reinterpret_cast<const float4*>(in + ((size_t)t * BP + b) * HH);
#pragma unroll
    for (int i = 0; i < 16; i++) {
        float4 v = src[i];
        h[4 * i + 0] = v.x; h[4 * i + 1] = v.y; h[4 * i + 2] = v.z; h[4 * i + 3] = v.w;
    }

    float h2[32];
#pragma unroll
    for (int j = 0; j < 32; j++) {
        float o = s_b1[j];
#pragma unroll
        for (int k = 0; k < 64; k++) o = fmaf(s_w1[j][k], h[k], o);
        h2[j] = fmaxf(o, 0.0f);
    }
    float* dst = outp + ((size_t)b * TT + t) * 4;
#pragma unroll
    for (int j = 0; j < 4; j++) {
        float o = s_b2[j];
#pragma unroll
        for (int k = 0; k < 32; k++) o = fmaf(s_w2[j][k], h2[k], o);
        dst[j] = o;
    }
}

// ---------------------------------------------------------------------------
extern "C" void kernel_launch(void* const* d_in, const int* in_sizes, int n_in,
                              void* d_out, int out_size)
{
    const float* x     = (const float*)d_in[0];
    const float* w1    = (const float*)d_in[1];
    const float* b1    = (const float*)d_in[2];
    const float* w2    = (const float*)d_in[3];
    const float* b2    = (const float*)d_in[4];
    const float* w_ih0 = (const float*)d_in[5];
    const float* w_hh0 = (const float*)d_in[6];
    const float* b_ih0 = (const float*)d_in[7];
    const float* b_hh0 = (const float*)d_in[8];
    const float* w_ih  = (const float*)d_in[9];   // (7, 256, 64)
    const float* w_hh  = (const float*)d_in[10];  // (7, 256, 64)
    const float* b_ih  = (const float*)d_in[11];  // (7, 256)
    const float* b_hh  = (const float*)d_in[12];  // (7, 256)
    const float* wo1   = (const float*)d_in[13];
    const float* bo1   = (const float*)d_in[14];
    const float* wo2   = (const float*)d_in[15];
    const float* bo2   = (const float*)d_in[16];
    float* outp = (float*)d_out;

    const int nelem = BB * TT;            // 131072
    mlp_in_kernel<<<nelem / 256, 256>>>(x, w1, b1, w2, b2);

    // layer 0: A(stride16) -> B
    lstm_kernel<16><<<NCTA, 512>>>(0, 1, w_ih0, w_hh0, b_ih0, b_hh0);

    // layers 1..7: ping-pong B->A->B->...
    int cur = 1;
    for (int l = 0; l < NL - 1; l++) {
        int nxt = cur ^ 1;
        lstm_kernel<64><<<NCTA, 512>>>(cur, nxt,
                                       w_ih + (size_t)l * GG * HH,
                                       w_hh + (size_t)l * GG * HH,
                                       b_ih + (size_t)l * GG,
                                       b_hh + (size_t)l * GG);
        cur = nxt;
    }

    mlp_out_kernel<<<nelem / 256, 256>>>(cur, wo1, bo1, wo2, bo2, outp);
}

// round 4
// speedup vs baseline: 1.1756x; 1.1756x over previous
#include <cuda_runtime.h>
#include <cuda_bf16.h>
#include <cstdint>

// Problem constants
#define BB 2048   // batch
#define BP 2058   // padded batch (147 CTAs * 14 rows)
#define TT 64     // timesteps
#define HH 64     // LSTM hidden
#define GG 256    // 4*H gates
#define NL 8      // LSTM layers
#define BT 14     // batch rows per CTA
#define RC 7      // row chunk (BT/2)
#define NCTA 147
#define NSPLIT 4  // K splits

// Ping-pong inter-layer buffers, layout [T, BP, H] (layer0 input uses [T, BP, 16])
__device__ float g_bufA[(size_t)TT * BP * HH + 256];
__device__ float g_bufB[(size_t)TT * BP * HH + 256];

__device__ __forceinline__ float* bufptr(int s) { return s ? g_bufB : g_bufA; }

__device__ __forceinline__ float sigm(float x) {
    return __fdividef(1.0f, 1.0f + __expf(-x));
}
__device__ __forceinline__ float tanh_(float x) {
    return __fdividef(2.0f, 1.0f + __expf(-2.0f * x)) - 1.0f;
}

// ---- packed f32x2 helpers (Blackwell FFMA2; PTX-only) ----
__device__ __forceinline__ void ffma2(uint64_t& d, uint64_t a, uint64_t b) {
    asm("fma.rn.f32x2 %0, %1, %2, %0;" : "+l"(d) : "l"(a), "l"(b));
}
__device__ __forceinline__ uint64_t pack2(float lo, float hi) {
    uint64_t r;
    asm("mov.b64 %0, {%1, %2};" : "=l"(r) : "f"(lo), "f"(hi));
    return r;
}
__device__ __forceinline__ float hsum2(uint64_t v) {
    float lo, hi;
    asm("mov.b64 {%0, %1}, %2;" : "=f"(lo), "=f"(hi) : "l"(v));
    return lo + hi;
}

// ---------------------------------------------------------------------------
// Input MLP: x[B,T,2] -> relu(x@w1^T+b1)@w2^T+b2 -> g_bufA as [T,BP,16]
// ---------------------------------------------------------------------------
__global__ void mlp_in_kernel(const float* __restrict__ x,
                              const float* __restrict__ w1, const float* __restrict__ b1,
                              const float* __restrict__ w2, const float* __restrict__ b2)
{
    __shared__ float s_w1[16][2], s_b1[16], s_w2[16][16], s_b2[16];
    int tid = threadIdx.x;
    if (tid < 32) { s_w1[tid / 2][tid % 2] = w1[tid]; }
    if (tid < 16) { s_b1[tid] = b1[tid]; s_b2[tid] = b2[tid]; }
    if (tid >= 32 && tid < 32 + 256) {
        int i = tid - 32;
        s_w2[i / 16][i % 16] = w2[i];
    }
    __syncthreads();

    int idx = blockIdx.x * blockDim.x + tid;      // 0 .. B*T-1, idx = b*T + t
    int b = idx / TT;
    int t = idx % TT;
    float x0 = x[(size_t)idx * 2 + 0];
    float x1 = x[(size_t)idx * 2 + 1];

    float h1[16];
#pragma unroll
    for (int j = 0; j < 16; j++) {
        float v = fmaf(s_w1[j][0], x0, fmaf(s_w1[j][1], x1, s_b1[j]));
        h1[j] = fmaxf(v, 0.0f);
    }
    float* dst = g_bufA + (size_t)t * BP * 16 + (size_t)b * 16;
#pragma unroll
    for (int j = 0; j < 16; j++) {
        float o = s_b2[j];
#pragma unroll
        for (int k = 0; k < 16; k++) o = fmaf(s_w2[j][k], h1[k], o);
        dst[j] = o;
    }
}

// ---------------------------------------------------------------------------
// One LSTM layer, 512 threads = 128 column-pair threads x 4 K-splits.
// Thread (p, q): gate cols jA=p, jB=p+128; K range [q*KH', (q+1)*KH') of
// K = concat(x_t[I], h[64]). Weights for both cols held as even/odd-k pairs
// in 64-bit regs (32 u64). Each LDS.128 of activations feeds 4 FFMA2
// (2 k-pairs x 2 cols) -> LDS traffic halved vs 1-col layout. Rows processed
// in two chunks of 7 to keep live accumulators at 14 u64.
// ---------------------------------------------------------------------------
template <int I>
__global__ void __launch_bounds__(512, 1)
lstm_kernel(int insel, int outsel,
            const float* __restrict__ w_ih, const float* __restrict__ w_hh,
            const float* __restrict__ b_ih, const float* __restrict__ b_hh)
{
    constexpr int KTOT = I + HH;          // 128 (layers 1..7), 80 (layer 0)
    constexpr int KH   = KTOT / NSPLIT;   // 32 / 20 per thread

    extern __shared__ float smem[];
    float* s_act = smem;                  // [BT][KTOT]  ([x_t | h])
    float* s_c   = s_act + BT * KTOT;     // [BT][HH]
    float* s_gp  = s_c + BT * HH;         // [NSPLIT][BT][GG]

    const float* in  = bufptr(insel);
    float*       out = bufptr(outsel);
    const int tid = threadIdx.x;
    const int p   = tid & 127;            // column-pair index
    const int q   = tid >> 7;             // K split (0..3); uniform within warp
    const int b0  = blockIdx.x * BT;
    const int jA  = p;
    const int jB  = p + 128;

    // Per-thread weight pairs: wA/wB[kk/2] = {w[j][k0], w[j][k0+1]}
    uint64_t wA[KH / 2], wB[KH / 2];
#pragma unroll
    for (int kk = 0; kk < KH; kk += 2) {
        int k0 = q * KH + kk;
        int k1 = k0 + 1;
        float a0 = (k0 < I) ? w_ih[(size_t)jA * I + k0] : w_hh[(size_t)jA * HH + (k0 - I)];
        float a1 = (k1 < I) ? w_ih[(size_t)jA * I + k1] : w_hh[(size_t)jA * HH + (k1 - I)];
        float c0 = (k0 < I) ? w_ih[(size_t)jB * I + k0] : w_hh[(size_t)jB * HH + (k0 - I)];
        float c1 = (k1 < I) ? w_ih[(size_t)jB * I + k1] : w_hh[(size_t)jB * HH + (k1 - I)];
        wA[kk / 2] = pack2(a0, a1);
        wB[kk / 2] = pack2(c0, c1);
    }
    const uint64_t biasA = (q == 0) ? pack2(b_ih[jA] + b_hh[jA], 0.0f) : 0ull;
    const uint64_t biasB = (q == 0) ? pack2(b_ih[jB] + b_hh[jB], 0.0f) : 0ull;

    // h0 = c0 = 0
    for (int i = tid; i < BT * HH; i += 512) {
        int r = i >> 6, u = i & 63;
        s_act[r * KTOT + I + u] = 0.0f;
        s_c[i] = 0.0f;
    }
    // stage x_0
    {
        const float4* src = reinterpret_cast<const float4*>(in + (size_t)b0 * I);
        for (int i = tid; i < BT * I / 4; i += 512) {
            float4 v = src[i];
            int r = (4 * i) / I, k = (4 * i) % I;
            *reinterpret_cast<float4*>(&s_act[r * KTOT + k]) = v;
        }
    }
    __syncthreads();

    const float* ap = s_act + q * KH;     // this thread's K window base

    for (int t = 0; t < TT; t++) {
        // --- gate partials: two row chunks of RC=7 ---
#pragma unroll
        for (int ch = 0; ch < 2; ch++) {
            const int r0 = ch * RC;
            uint64_t accA[RC], accB[RC];
#pragma unroll
            for (int r = 0; r < RC; r++) { accA[r] = biasA; accB[r] = biasB; }

#pragma unroll
            for (int kk = 0; kk < KH; kk += 4) {
#pragma unroll
                for (int r = 0; r < RC; r++) {
                    ulonglong2 v = *reinterpret_cast<const ulonglong2*>(
                        ap + (size_t)(r0 + r) * KTOT + kk);        // LDS.128 broadcast
                    ffma2(accA[r], v.x, wA[kk / 2]);
                    ffma2(accA[r], v.y, wA[kk / 2 + 1]);
                    ffma2(accB[r], v.x, wB[kk / 2]);
                    ffma2(accB[r], v.y, wB[kk / 2 + 1]);
                }
            }
            float* gpq = s_gp + ((size_t)q * BT) * GG;
#pragma unroll
            for (int r = 0; r < RC; r++) {
                gpq[(size_t)(r0 + r) * GG + jA] = hsum2(accA[r]);
                gpq[(size_t)(r0 + r) * GG + jB] = hsum2(accB[r]);
            }
        }
        __syncthreads();

        // --- elementwise update: BT*64 = 896 (row, unit) pairs over 512 threads ---
#pragma unroll
        for (int pp = 0; pp < 2; pp++) {
            int ul = pp * 512 + tid;
            if (ul < BT * HH) {
                int r = ul >> 6;
                int u = ul & 63;
                float gi = 0.f, gf = 0.f, gg = 0.f, go = 0.f;
#pragma unroll
                for (int s = 0; s < NSPLIT; s++) {
                    const float* gp = s_gp + ((size_t)s * BT + r) * GG;
                    gi += gp[u];
                    gf += gp[64 + u];
                    gg += gp[128 + u];
                    go += gp[192 + u];
                }
                float iv = sigm(gi);
                float fv = sigm(gf);
                float gv = tanh_(gg);
                float ov = sigm(go);
                float c  = fmaf(fv, s_c[r * HH + u], iv * gv);
                float h  = ov * tanh_(c);
                s_c[r * HH + u] = c;
                s_act[r * KTOT + I + u] = h;
                out[(size_t)t * BP * HH + (size_t)(b0 + r) * HH + u] = h;
            }
        }
        // stage x_{t+1} (mainloop reads of step t finished: guarded by sync above)
        if (t + 1 < TT) {
            const float4* src = reinterpret_cast<const float4*>(in + (size_t)(t + 1) * BP * I + (size_t)b0 * I);
            for (int i = tid; i < BT * I / 4; i += 512) {
                float4 v = src[i];
                int r = (4 * i) / I, k = (4 * i) % I;
                *reinterpret_cast<float4*>(&s_act[r * KTOT + k]) = v;
            }
        }
        __syncthreads();
    }
}

// ---------------------------------------------------------------------------
// Output MLP: h[T,BP,64] -> relu(h@wo1^T+bo1)@wo2^T+bo2 -> out[B,T,4]
// ---------------------------------------------------------------------------
__global__ void mlp_out_kernel(int insel,
                               const float* __restrict__ wo1, const float* __restrict__ bo1,
                               const float* __restrict__ wo2, const float* __restrict__ bo2,
                               float* __restrict__ outp)
{
    __shared__ float s_w1[32][64];
    __shared__ float s_b1[32];
    __shared__ float s_w2[4][32];
    __shared__ float s_b2[4];
    int tid = threadIdx.x;
    for (int i = tid; i < 32 * 64; i += 256) s_w1[i / 64][i % 64] = wo1[i];
    if (tid < 32) s_b1[tid] = bo1[tid];
    if (tid < 128) s_w2[tid / 32][tid % 32] = wo2[tid];
    if (tid < 4) s_b2[tid] = bo2[tid];
    __syncthreads();

    const float* in = bufptr(insel);
    int idx = blockIdx.x * blockDim.x + tid;   // idx = t*B + b (coalesced h reads)
    int t = idx / BB;
    int b = idx % BB;

    float h[64];
    const float4* src = reinterpret_cast<const float4*>(in + ((size_t)t * BP + b) * HH);
#pragma unroll
    for (int i = 0; i < 16; i++) {
        float4 v = src[i];
        h[4 * i + 0] = v.x; h[4 * i + 1] = v.y; h[4 * i + 2] = v.z; h[4 * i + 3] = v.w;
    }

    float h2[32];
#pragma unroll
    for (int j = 0; j < 32; j++) {
        float o = s_b1[j];
#pragma unroll
        for (int k = 0; k < 64; k++) o = fmaf(s_w1[j][k], h[k], o);
        h2[j] = fmaxf(o, 0.0f);
    }
    float* dst = outp + ((size_t)b * TT + t) * 4;
#pragma unroll
    for (int j = 0; j < 4; j++) {
        float o = s_b2[j];
#pragma unroll
        for (int k = 0; k < 32; k++) o = fmaf(s_w2[j][k], h2[k], o);
        dst[j] = o;
    }
}

// ---------------------------------------------------------------------------
extern "C" void kernel_launch(void* const* d_in, const int* in_sizes, int n_in,
                              void* d_out, int out_size)
{
    const float* x     = (const float*)d_in[0];
    const float* w1    = (const float*)d_in[1];
    const float* b1    = (const float*)d_in[2];
    const float* w2    = (const float*)d_in[3];
    const float* b2    = (const float*)d_in[4];
    const float* w_ih0 = (const float*)d_in[5];
    const float* w_hh0 = (const float*)d_in[6];
    const float* b_ih0 = (const float*)d_in[7];
    const float* b_hh0 = (const float*)d_in[8];
    const float* w_ih  = (const float*)d_in[9];   // (7, 256, 64)
    const float* w_hh  = (const float*)d_in[10];  // (7, 256, 64)
    const float* b_ih  = (const float*)d_in[11];  // (7, 256)
    const float* b_hh  = (const float*)d_in[12];  // (7, 256)
    const float* wo1   = (const float*)d_in[13];
    const float* bo1   = (const float*)d_in[14];
    const float* wo2   = (const float*)d_in[15];
    const float* bo2   = (const float*)d_in[16];
    float* outp = (float*)d_out;

    // dynamic smem sizes
    const int smem16 = (BT * (16 + HH) + BT * HH + NSPLIT * BT * GG) * 4;   // layer 0
    const int smem64 = (BT * (HH + HH) + BT * HH + NSPLIT * BT * GG) * 4;   // layers 1..7
    cudaFuncSetAttribute(lstm_kernel<16>, cudaFuncAttributeMaxDynamicSharedMemorySize, smem16);
    cudaFuncSetAttribute(lstm_kernel<64>, cudaFuncAttributeMaxDynamicSharedMemorySize, smem64);

    const int nelem = BB * TT;            // 131072
    mlp_in_kernel<<<nelem / 256, 256>>>(x, w1, b1, w2, b2);

    // layer 0: A(stride16) -> B
    lstm_kernel<16><<<NCTA, 512, smem16>>>(0, 1, w_ih0, w_hh0, b_ih0, b_hh0);

    // layers 1..7: ping-pong B->A->B->...
    int cur = 1;
    for (int l = 0; l < NL - 1; l++) {
        int nxt = cur ^ 1;
        lstm_kernel<64><<<NCTA, 512, smem64>>>(cur, nxt,
                                               w_ih + (size_t)l * GG * HH,
                                               w_hh + (size_t)l * GG * HH,
                                               b_ih + (size_t)l * GG,
                                               b_hh + (size_t)l * GG);
        cur = nxt;
    }

    mlp_out_kernel<<<nelem / 256, 256>>>(cur, wo1, bo1, wo2, bo2, outp);
}